// round 9
// baseline (speedup 1.0000x reference)
#include <cuda_runtime.h>
#include <cuda_fp16.h>
#include <cstdint>

#define N_NODES  100000
#define N_EDGES  1600000
#define N_GRAPHS 256
#define F_IN     38
#define FP       40      // padded feature width (80B half rows)
#define HID      64
#define NREP     32      // replicated graph buckets
#define NSB      98      // scan blocks (98*1024 = 100352 bins >= N_NODES)
#define NBINS    (NSB * 1024)
#define CHUNK    64      // edges per warp in sorted-consume kernels

typedef unsigned long long ull;

// ---------------- scratch (static device globals; zero at load) --------------
// Invariant: every kernel that consumes a scratch array restores it to zero,
// so each call of kernel_launch sees the same initial state (deterministic).
__device__ __align__(256) __half   g_xh  [N_NODES * FP];          // 8 MB
__device__ __align__(256) float    g_agg1[N_NODES * FP];          // 16 MB (node1 re-zeros)
__device__ __align__(256) __half   g_h1h [N_NODES * HID];         // 12.8MB (overwritten)
__device__ __align__(256) float    g_S2  [NREP * N_GRAPHS * HID]; // 2 MB (final re-zeros)
__device__ __align__(256) float    g_Shr [NREP * N_GRAPHS * HID]; // 2 MB (final re-zeros)
__device__ __align__(256) float    g_cntr[NREP * N_GRAPHS];       // 32 KB (final re-zeros)
__device__ __align__(256) unsigned g_dcnt[NBINS];                 // 400 KB (scan1 re-zeros)
__device__ __align__(256) unsigned g_base[NBINS];                 // 400 KB (overwritten)
__device__ __align__(256) unsigned g_bsum[128];                   // (overwritten)
__device__ __align__(256) ull      g_rec [N_EDGES];               // 12.8 MB (overwritten)

// ---------------- helpers ----------------------------------------------------
__device__ __forceinline__ void red4(float* p, float a, float b, float c, float d) {
    asm volatile("red.global.add.v4.f32 [%0], {%1,%2,%3,%4};"
                 :: "l"(p), "f"(a), "f"(b), "f"(c), "f"(d));
}
__device__ __forceinline__ void red2(float* p, float a, float b) {
    asm volatile("red.global.add.v2.f32 [%0], {%1,%2};"
                 :: "l"(p), "f"(a), "f"(b));
}
__device__ __forceinline__ ull pk2(float a) {
    ull r; asm("mov.b64 %0, {%1, %1};" : "=l"(r) : "f"(a)); return r;
}
__device__ __forceinline__ void fma2(ull& d, ull a, ull b) {
    asm("fma.rn.f32x2 %0, %1, %2, %0;" : "+l"(d) : "l"(a), "l"(b));
}
__device__ __forceinline__ float2 upk2(ull v) {
    float2 f; asm("mov.b64 {%0, %1}, %2;" : "=f"(f.x), "=f"(f.y) : "l"(v)); return f;
}

// ---------------- K0: pad-convert x to half (only remaining init work) -------
__global__ void k_init(const float* __restrict__ x) {
    int stride = gridDim.x * blockDim.x;
    int tid    = blockIdx.x * blockDim.x + threadIdx.x;
    for (int i = tid; i < N_NODES * FP; i += stride) {
        int n = i / FP;
        int c = i - n * FP;
        g_xh[i] = (c < F_IN) ? __float2half(x[n * F_IN + c]) : __half(0.0f);
    }
}

// ---------------- S1: histogram over dst -------------------------------------
__global__ void k_hist(const int* __restrict__ ei) {
    int stride = gridDim.x * blockDim.x;
    for (int e = blockIdx.x * blockDim.x + threadIdx.x; e < N_EDGES; e += stride)
        atomicAdd(&g_dcnt[ei[N_EDGES + e]], 1u);
}

// ---------------- S2: per-block exclusive scan + self-zero g_dcnt ------------
__global__ void k_scan1() {
    __shared__ unsigned s[1024];
    int b = blockIdx.x, t = threadIdx.x;
    int i = b * 1024 + t;
    unsigned v = g_dcnt[i];
    g_dcnt[i] = 0u;                       // restore for next call
    s[t] = v;
    __syncthreads();
    for (int off = 1; off < 1024; off <<= 1) {
        unsigned a = (t >= off) ? s[t - off] : 0u;
        __syncthreads();
        s[t] += a;
        __syncthreads();
    }
    g_base[i] = s[t] - v;                 // exclusive
    if (t == 1023) g_bsum[b] = s[t];      // block total
}

// ---------------- S3: add block offsets (parallel shared scan) ---------------
__global__ void k_scan2() {
    __shared__ unsigned sb[128];
    int b = blockIdx.x, t = threadIdx.x;
    if (t < 128) sb[t] = (t < NSB) ? g_bsum[t] : 0u;
    __syncthreads();
    for (int off = 1; off < 128; off <<= 1) {
        unsigned a = (t < 128 && t >= off) ? sb[t - off] : 0u;
        __syncthreads();
        if (t < 128) sb[t] += a;
        __syncthreads();
    }
    unsigned soff = (b == 0) ? 0u : sb[b - 1];
    g_base[b * 1024 + t] += soff;
}

// ---------------- S4: scatter edges into dst-sorted records ------------------
// record: src [0..19] | dst [20..39] | g [40..47]
__global__ void k_scatter(const int* __restrict__ ei, const int* __restrict__ batch) {
    int stride = gridDim.x * blockDim.x;
    for (int e = blockIdx.x * blockDim.x + threadIdx.x; e < N_EDGES; e += stride) {
        unsigned src = (unsigned)ei[e];
        unsigned dst = (unsigned)ei[N_EDGES + e];
        unsigned g   = (unsigned)batch[dst];
        unsigned pos = atomicAdd(&g_base[dst], 1u);   // base array doubles as cursor
        g_rec[pos] = (ull)src | ((ull)dst << 20) | ((ull)g << 40);
    }
}

// ---------------- K1: sorted layer-1 aggregation -----------------------------
// warp walks CHUNK consecutive edges, 4 records per iteration (batched gathers)
__global__ void k_edge1s() {
    int t    = blockIdx.x * blockDim.x + threadIdx.x;
    int w    = t >> 5;
    int lane = t & 31;
    int e0   = w * CHUNK;
    if (e0 >= N_EDGES) return;                         // exact division
    bool act = lane < FP / 2;
    const __half2* X = (const __half2*)g_xh;

    float ax = 0.f, ay = 0.f;
    int cur = -1;
#pragma unroll 4
    for (int gr = 0; gr < CHUNK / 4; gr++) {
        int e = e0 + gr * 4;
        ulonglong2 rA = *(const ulonglong2*)(g_rec + e);
        ulonglong2 rB = *(const ulonglong2*)(g_rec + e + 2);
        int s0 = (int)(rA.x & 0xFFFFF), d0 = (int)((rA.x >> 20) & 0xFFFFF);
        int s1 = (int)(rA.y & 0xFFFFF), d1 = (int)((rA.y >> 20) & 0xFFFFF);
        int s2 = (int)(rB.x & 0xFFFFF), d2 = (int)((rB.x >> 20) & 0xFFFFF);
        int s3 = (int)(rB.y & 0xFFFFF), d3 = (int)((rB.y >> 20) & 0xFFFFF);
        float2 f0 = {0,0}, f1 = {0,0}, f2 = {0,0}, f3 = {0,0};
        if (act) {
            f0 = __half22float2(X[(size_t)s0 * (FP/2) + lane]);
            f1 = __half22float2(X[(size_t)s1 * (FP/2) + lane]);
            f2 = __half22float2(X[(size_t)s2 * (FP/2) + lane]);
            f3 = __half22float2(X[(size_t)s3 * (FP/2) + lane]);
        }
        if (d0 != cur) { if (cur >= 0 && act) red2(g_agg1 + (size_t)cur * FP + lane*2, ax, ay);
                         ax = 0.f; ay = 0.f; cur = d0; }
        ax += f0.x; ay += f0.y;
        if (d1 != cur) { if (act) red2(g_agg1 + (size_t)cur * FP + lane*2, ax, ay);
                         ax = 0.f; ay = 0.f; cur = d1; }
        ax += f1.x; ay += f1.y;
        if (d2 != cur) { if (act) red2(g_agg1 + (size_t)cur * FP + lane*2, ax, ay);
                         ax = 0.f; ay = 0.f; cur = d2; }
        ax += f2.x; ay += f2.y;
        if (d3 != cur) { if (act) red2(g_agg1 + (size_t)cur * FP + lane*2, ax, ay);
                         ax = 0.f; ay = 0.f; cur = d3; }
        ax += f3.x; ay += f3.y;
    }
    if (cur >= 0 && act) red2(g_agg1 + (size_t)cur * FP + lane*2, ax, ay);
}

// ---------------- K2: node transform + fused pooling + agg1 re-zero ----------
__global__ __launch_bounds__(128) void k_node1(const float* __restrict__ w_rel,
                                               const float* __restrict__ b,
                                               const float* __restrict__ w_root,
                                               const int*   __restrict__ batch) {
    __shared__ __align__(16) float sW[FP * HID * 2 + HID];
    float* sWrel  = sW;
    float* sWroot = sW + FP * HID;
    float* sB     = sW + 2 * FP * HID;
    for (int i = threadIdx.x; i < FP * HID; i += blockDim.x) {
        int k = i / HID;
        int c = i - k * HID;
        sWrel[i]  = (k < F_IN) ? w_rel [k * HID + c] : 0.0f;
        sWroot[i] = (k < F_IN) ? w_root[k * HID + c] : 0.0f;
    }
    for (int i = threadIdx.x; i < HID; i += blockDim.x) sB[i] = b[i];
    __syncthreads();

    int n = blockIdx.x * blockDim.x + threadIdx.x;
    if (n >= N_NODES) return;

    ull acc2[HID / 2];
#pragma unroll
    for (int j = 0; j < HID / 2; j++) acc2[j] = ((const ull*)sB)[j];

    float4*       arw = (float4*)(g_agg1 + (size_t)n * FP);
    const uint4*  xrh = (const uint4*) (g_xh   + (size_t)n * FP);
    float4 z4 = make_float4(0.f, 0.f, 0.f, 0.f);

    for (int ch = 0; ch < 5; ch++) {
        float4 a0 = arw[2 * ch];
        float4 a1 = arw[2 * ch + 1];
        arw[2 * ch]     = z4;              // restore zeros for next call
        arw[2 * ch + 1] = z4;
        uint4  xv = xrh[ch];
        const __half2* hp = (const __half2*)&xv;
        float av[8] = {a0.x, a0.y, a0.z, a0.w, a1.x, a1.y, a1.z, a1.w};
        float xf[8];
#pragma unroll
        for (int j = 0; j < 4; j++) {
            float2 f = __half22float2(hp[j]);
            xf[2 * j] = f.x; xf[2 * j + 1] = f.y;
        }
#pragma unroll
        for (int kk = 0; kk < 8; kk++) {
            int k = ch * 8 + kk;
            ull a2 = pk2(av[kk]);
            ull x2 = pk2(xf[kk]);
            const ulonglong2* wr = (const ulonglong2*)(sWrel  + k * HID);
            const ulonglong2* wo = (const ulonglong2*)(sWroot + k * HID);
#pragma unroll
            for (int c4 = 0; c4 < HID / 4; c4++) {
                ulonglong2 w = wr[c4];
                ulonglong2 u = wo[c4];
                fma2(acc2[2 * c4],     a2, w.x);
                fma2(acc2[2 * c4 + 1], a2, w.y);
                fma2(acc2[2 * c4],     x2, u.x);
                fma2(acc2[2 * c4 + 1], x2, u.y);
            }
        }
    }

    float val[HID];
#pragma unroll
    for (int j = 0; j < HID / 2; j++) {
        float2 f = upk2(acc2[j]);
        val[2 * j]     = fmaxf(f.x, 0.0f);
        val[2 * j + 1] = fmaxf(f.y, 0.0f);
    }

    uint4* out = (uint4*)(g_h1h + (size_t)n * HID);
#pragma unroll
    for (int q = 0; q < 8; q++) {
        uint4 o;
        unsigned* op = (unsigned*)&o;
#pragma unroll
        for (int j = 0; j < 4; j++) {
            __half2 h = __floats2half2_rn(val[q * 8 + 2 * j], val[q * 8 + 2 * j + 1]);
            op[j] = *(unsigned*)&h;
        }
        out[q] = o;
    }

    int g = batch[n];
    int r = n & (NREP - 1);
    float* base = g_Shr + ((size_t)(r * N_GRAPHS + g)) * HID;
#pragma unroll
    for (int i = 0; i < HID / 4; i++)
        red4(base + 4 * i, val[4 * i], val[4 * i + 1], val[4 * i + 2], val[4 * i + 3]);
    atomicAdd(&g_cntr[r * N_GRAPHS + g], 1.0f);
}

// ---------------- K3: sorted layer-2 aggregation (g non-decreasing) ----------
__global__ void k_edge2s() {
    int t    = blockIdx.x * blockDim.x + threadIdx.x;
    int w    = t >> 5;
    int lane = t & 31;
    int e0   = w * CHUNK;
    if (e0 >= N_EDGES) return;
    int r = w & (NREP - 1);
    const __half2* H = (const __half2*)g_h1h;

    float ax = 0.f, ay = 0.f;
    int cur = -1;
#pragma unroll 4
    for (int gr = 0; gr < CHUNK / 4; gr++) {
        int e = e0 + gr * 4;
        ulonglong2 rA = *(const ulonglong2*)(g_rec + e);
        ulonglong2 rB = *(const ulonglong2*)(g_rec + e + 2);
        int s0 = (int)(rA.x & 0xFFFFF), g0 = (int)((rA.x >> 40) & 0xFF);
        int s1 = (int)(rA.y & 0xFFFFF), g1 = (int)((rA.y >> 40) & 0xFF);
        int s2 = (int)(rB.x & 0xFFFFF), g2 = (int)((rB.x >> 40) & 0xFF);
        int s3 = (int)(rB.y & 0xFFFFF), g3 = (int)((rB.y >> 40) & 0xFF);
        float2 f0 = __half22float2(H[(size_t)s0 * (HID/2) + lane]);
        float2 f1 = __half22float2(H[(size_t)s1 * (HID/2) + lane]);
        float2 f2 = __half22float2(H[(size_t)s2 * (HID/2) + lane]);
        float2 f3 = __half22float2(H[(size_t)s3 * (HID/2) + lane]);
        if (g0 != cur) { if (cur >= 0) red2(g_S2 + ((size_t)(r*N_GRAPHS+cur))*HID + lane*2, ax, ay);
                         ax = 0.f; ay = 0.f; cur = g0; }
        ax += f0.x; ay += f0.y;
        if (g1 != cur) { red2(g_S2 + ((size_t)(r*N_GRAPHS+cur))*HID + lane*2, ax, ay);
                         ax = 0.f; ay = 0.f; cur = g1; }
        ax += f1.x; ay += f1.y;
        if (g2 != cur) { red2(g_S2 + ((size_t)(r*N_GRAPHS+cur))*HID + lane*2, ax, ay);
                         ax = 0.f; ay = 0.f; cur = g2; }
        ax += f2.x; ay += f2.y;
        if (g3 != cur) { red2(g_S2 + ((size_t)(r*N_GRAPHS+cur))*HID + lane*2, ax, ay);
                         ax = 0.f; ay = 0.f; cur = g3; }
        ax += f3.x; ay += f3.y;
    }
    if (cur >= 0) red2(g_S2 + ((size_t)(r*N_GRAPHS+cur))*HID + lane*2, ax, ay);
}

// ---------------- K4: reduce replicas + tiny GEMM + mean + relu + re-zero ----
__global__ void k_final(const float* __restrict__ w2_rel,
                        const float* __restrict__ b2,
                        const float* __restrict__ w2_root,
                        float* __restrict__ out) {
    int g = blockIdx.x;
    int c = threadIdx.x;
    __shared__ float sA[HID];
    __shared__ float sH[HID];
    __shared__ float sc;

    float s2 = 0.0f, sh = 0.0f;
#pragma unroll
    for (int r = 0; r < NREP; r++) {
        size_t i = ((size_t)(r * N_GRAPHS + g)) * HID + c;
        s2 += g_S2[i];
        sh += g_Shr[i];
        g_S2[i]  = 0.0f;                  // restore for next call
        g_Shr[i] = 0.0f;
    }
    sA[c] = s2;
    sH[c] = sh;
    if (c == 0) {
        float n = 0.0f;
#pragma unroll
        for (int r = 0; r < NREP; r++) {
            n += g_cntr[r * N_GRAPHS + g];
            g_cntr[r * N_GRAPHS + g] = 0.0f;
        }
        sc = n;
    }
    __syncthreads();

    float acc = 0.0f;
#pragma unroll 8
    for (int k = 0; k < HID; k++)
        acc += sA[k] * w2_rel[k * HID + c] + sH[k] * w2_root[k * HID + c];

    float n = sc;
    acc += n * b2[c];
    out[g * HID + c] = fmaxf(acc / fmaxf(n, 1.0f), 0.0f);
}

// ---------------- launch -----------------------------------------------------
extern "C" void kernel_launch(void* const* d_in, const int* in_sizes, int n_in,
                              void* d_out, int out_size) {
    const float* x       = (const float*)d_in[0];
    const int*   ei      = (const int*)d_in[1];
    const int*   batch   = (const int*)d_in[2];
    const float* w1_rel  = (const float*)d_in[3];
    const float* b1_rel  = (const float*)d_in[4];
    const float* w1_root = (const float*)d_in[5];
    const float* w2_rel  = (const float*)d_in[6];
    const float* b2_rel  = (const float*)d_in[7];
    const float* w2_root = (const float*)d_in[8];
    float*       out     = (float*)d_out;

    int nwarp = N_EDGES / CHUNK;                       // 25000, exact
    int ncta  = (nwarp * 32 + 255) / 256;              // 3125

    k_init   <<<2048, 256>>>(x);
    k_hist   <<<2048, 256>>>(ei);
    k_scan1  <<<NSB, 1024>>>();
    k_scan2  <<<NSB, 1024>>>();
    k_scatter<<<2048, 256>>>(ei, batch);
    k_edge1s <<<ncta, 256>>>();
    k_node1  <<<(N_NODES + 127) / 128, 128>>>(w1_rel, b1_rel, w1_root, batch);
    k_edge2s <<<ncta, 256>>>();
    k_final  <<<N_GRAPHS, HID>>>(w2_rel, b2_rel, w2_root, out);
}

// round 10
// speedup vs baseline: 1.4517x; 1.4517x over previous
#include <cuda_runtime.h>
#include <cuda_fp16.h>
#include <cstdint>

#define N_NODES  100000
#define N_EDGES  1600000
#define N_GRAPHS 256
#define F_IN     38
#define FP       40      // padded feature width (80B half rows)
#define HID      64
#define NREP     32      // replicated graph buckets
#define NSB      98      // scan blocks (98*1024 = 100352 bins >= N_NODES)
#define NBINS    (NSB * 1024)
#define CHUNK    128     // edges per warp in sorted-consume kernels

typedef unsigned long long ull;

// ---------------- scratch (static device globals; zero at load) --------------
__device__ __align__(256) __half   g_xh  [N_NODES * FP];          // 8 MB
__device__ __align__(256) float    g_agg1[N_NODES * FP];          // 16 MB
__device__ __align__(256) __half   g_h1h [N_NODES * HID];         // 12.8MB
__device__ __align__(256) float    g_S2  [NREP * N_GRAPHS * HID]; // 2 MB
__device__ __align__(256) float    g_Shr [NREP * N_GRAPHS * HID]; // 2 MB
__device__ __align__(256) float    g_cntr[NREP * N_GRAPHS];       // 32 KB
__device__ __align__(256) unsigned g_dcnt[NBINS];                 // 400 KB (scan1 self-zeros)
__device__ __align__(256) unsigned g_base[NBINS];                 // 400 KB
__device__ __align__(256) unsigned g_bsum[128];
__device__ __align__(256) ull      g_rec [N_EDGES];               // 12.8 MB

// ---------------- helpers ----------------------------------------------------
__device__ __forceinline__ void red4(float* p, float a, float b, float c, float d) {
    asm volatile("red.global.add.v4.f32 [%0], {%1,%2,%3,%4};"
                 :: "l"(p), "f"(a), "f"(b), "f"(c), "f"(d));
}
__device__ __forceinline__ void red2(float* p, float a, float b) {
    asm volatile("red.global.add.v2.f32 [%0], {%1,%2};"
                 :: "l"(p), "f"(a), "f"(b));
}
__device__ __forceinline__ ull pk2(float a) {
    ull r; asm("mov.b64 %0, {%1, %1};" : "=l"(r) : "f"(a)); return r;
}
__device__ __forceinline__ void fma2(ull& d, ull a, ull b) {
    asm("fma.rn.f32x2 %0, %1, %2, %0;" : "+l"(d) : "l"(a), "l"(b));
}
__device__ __forceinline__ float2 upk2(ull v) {
    float2 f; asm("mov.b64 {%0, %1}, %2;" : "=f"(f.x), "=f"(f.y) : "l"(v)); return f;
}

// ---------------- K0: zero scratch + pad-convert x + FUSED dst histogram -----
// g_dcnt is NOT zeroed here (race with hist) — k_scan1 self-zeros it, and it
// is zero at module load, so every call sees g_dcnt == 0 on entry.
__global__ void k_init(const float* __restrict__ x, const int* __restrict__ ei) {
    int stride = gridDim.x * blockDim.x;
    int tid    = blockIdx.x * blockDim.x + threadIdx.x;
    for (int i = tid; i < N_NODES * FP; i += stride) {
        int n = i / FP;
        int c = i - n * FP;
        g_xh[i] = (c < F_IN) ? __float2half(x[n * F_IN + c]) : __half(0.0f);
    }
    float4 z4 = make_float4(0.f, 0.f, 0.f, 0.f);
    for (int i = tid; i < N_NODES * FP / 4; i += stride)          ((float4*)g_agg1)[i] = z4;
    for (int i = tid; i < NREP * N_GRAPHS * HID / 4; i += stride) {
        ((float4*)g_S2)[i]  = z4;
        ((float4*)g_Shr)[i] = z4;
    }
    for (int i = tid; i < NREP * N_GRAPHS; i += stride)           g_cntr[i] = 0.0f;
    for (int e = tid; e < N_EDGES; e += stride)                   // fused histogram
        atomicAdd(&g_dcnt[ei[N_EDGES + e]], 1u);
}

// ---------------- S2: per-block exclusive scan + self-zero g_dcnt ------------
__global__ void k_scan1() {
    __shared__ unsigned s[1024];
    int b = blockIdx.x, t = threadIdx.x;
    int i = b * 1024 + t;
    unsigned v = g_dcnt[i];
    g_dcnt[i] = 0u;                       // restore invariant for next call
    s[t] = v;
    __syncthreads();
    for (int off = 1; off < 1024; off <<= 1) {
        unsigned a = (t >= off) ? s[t - off] : 0u;
        __syncthreads();
        s[t] += a;
        __syncthreads();
    }
    g_base[i] = s[t] - v;                 // exclusive
    if (t == 1023) g_bsum[b] = s[t];      // block total
}

// ---------------- S3: add block offsets (R7-exact serial: clock canary) ------
__global__ void k_scan2() {
    __shared__ unsigned sb[128];
    __shared__ unsigned soff;
    int b = blockIdx.x, t = threadIdx.x;
    if (t < NSB) sb[t] = g_bsum[t];
    __syncthreads();
    if (t == 0) {
        unsigned s = 0;
        for (int i = 0; i < b; i++) s += sb[i];
        soff = s;
    }
    __syncthreads();
    g_base[b * 1024 + t] += soff;
}

// ---------------- S4: scatter edges into dst-sorted records ------------------
// record: src [0..19] | dst [20..39] | g [40..47]
__global__ void k_scatter(const int* __restrict__ ei, const int* __restrict__ batch) {
    int stride = gridDim.x * blockDim.x;
    for (int e = blockIdx.x * blockDim.x + threadIdx.x; e < N_EDGES; e += stride) {
        unsigned src = (unsigned)ei[e];
        unsigned dst = (unsigned)ei[N_EDGES + e];
        unsigned g   = (unsigned)batch[dst];
        unsigned pos = atomicAdd(&g_base[dst], 1u);   // base array doubles as cursor
        g_rec[pos] = (ull)src | ((ull)dst << 20) | ((ull)g << 40);
    }
}

// ---------------- K1: sorted layer-1 aggregation (R7-exact) ------------------
__global__ void k_edge1s() {
    int t    = blockIdx.x * blockDim.x + threadIdx.x;
    int w    = t >> 5;
    int lane = t & 31;
    int e0   = w * CHUNK;
    if (e0 >= N_EDGES) return;                         // exact division
    float ax = 0.f, ay = 0.f;
    int cur = -1;
    const ull* R = g_rec;
#pragma unroll 4
    for (int e = e0; e < e0 + CHUNK; e += 2) {
        ulonglong2 rr = *(const ulonglong2*)(R + e);
        int srcA = (int)(rr.x & 0xFFFFF), dstA = (int)((rr.x >> 20) & 0xFFFFF);
        int srcB = (int)(rr.y & 0xFFFFF), dstB = (int)((rr.y >> 20) & 0xFFFFF);
        float2 fA = make_float2(0.f, 0.f), fB = make_float2(0.f, 0.f);
        if (lane < FP / 2) {
            fA = __half22float2(*(const __half2*)(g_xh + (size_t)srcA * FP + lane * 2));
            fB = __half22float2(*(const __half2*)(g_xh + (size_t)srcB * FP + lane * 2));
        }
        if (dstA != cur) {
            if (cur >= 0 && lane < FP / 2) red2(g_agg1 + (size_t)cur * FP + lane * 2, ax, ay);
            ax = 0.f; ay = 0.f; cur = dstA;
        }
        ax += fA.x; ay += fA.y;
        if (dstB != cur) {
            if (lane < FP / 2) red2(g_agg1 + (size_t)cur * FP + lane * 2, ax, ay);
            ax = 0.f; ay = 0.f; cur = dstB;
        }
        ax += fB.x; ay += fB.y;
    }
    if (cur >= 0 && lane < FP / 2) red2(g_agg1 + (size_t)cur * FP + lane * 2, ax, ay);
}

// ---------------- K2: node transform + fused pooling (R7-exact) --------------
__global__ __launch_bounds__(128) void k_node1(const float* __restrict__ w_rel,
                                               const float* __restrict__ b,
                                               const float* __restrict__ w_root,
                                               const int*   __restrict__ batch) {
    __shared__ __align__(16) float sW[FP * HID * 2 + HID];
    float* sWrel  = sW;
    float* sWroot = sW + FP * HID;
    float* sB     = sW + 2 * FP * HID;
    for (int i = threadIdx.x; i < FP * HID; i += blockDim.x) {
        int k = i / HID;
        int c = i - k * HID;
        sWrel[i]  = (k < F_IN) ? w_rel [k * HID + c] : 0.0f;
        sWroot[i] = (k < F_IN) ? w_root[k * HID + c] : 0.0f;
    }
    for (int i = threadIdx.x; i < HID; i += blockDim.x) sB[i] = b[i];
    __syncthreads();

    int n = blockIdx.x * blockDim.x + threadIdx.x;
    if (n >= N_NODES) return;

    ull acc2[HID / 2];
#pragma unroll
    for (int j = 0; j < HID / 2; j++) acc2[j] = ((const ull*)sB)[j];

    const float4* ar  = (const float4*)(g_agg1 + (size_t)n * FP);
    const uint4*  xrh = (const uint4*) (g_xh   + (size_t)n * FP);

    for (int ch = 0; ch < 5; ch++) {
        float4 a0 = ar[2 * ch];
        float4 a1 = ar[2 * ch + 1];
        uint4  xv = xrh[ch];
        const __half2* hp = (const __half2*)&xv;
        float av[8] = {a0.x, a0.y, a0.z, a0.w, a1.x, a1.y, a1.z, a1.w};
        float xf[8];
#pragma unroll
        for (int j = 0; j < 4; j++) {
            float2 f = __half22float2(hp[j]);
            xf[2 * j] = f.x; xf[2 * j + 1] = f.y;
        }
#pragma unroll
        for (int kk = 0; kk < 8; kk++) {
            int k = ch * 8 + kk;
            ull a2 = pk2(av[kk]);
            ull x2 = pk2(xf[kk]);
            const ulonglong2* wr = (const ulonglong2*)(sWrel  + k * HID);
            const ulonglong2* wo = (const ulonglong2*)(sWroot + k * HID);
#pragma unroll
            for (int c4 = 0; c4 < HID / 4; c4++) {
                ulonglong2 w = wr[c4];
                ulonglong2 u = wo[c4];
                fma2(acc2[2 * c4],     a2, w.x);
                fma2(acc2[2 * c4 + 1], a2, w.y);
                fma2(acc2[2 * c4],     x2, u.x);
                fma2(acc2[2 * c4 + 1], x2, u.y);
            }
        }
    }

    float val[HID];
#pragma unroll
    for (int j = 0; j < HID / 2; j++) {
        float2 f = upk2(acc2[j]);
        val[2 * j]     = fmaxf(f.x, 0.0f);
        val[2 * j + 1] = fmaxf(f.y, 0.0f);
    }

    uint4* out = (uint4*)(g_h1h + (size_t)n * HID);
#pragma unroll
    for (int q = 0; q < 8; q++) {
        uint4 o;
        unsigned* op = (unsigned*)&o;
#pragma unroll
        for (int j = 0; j < 4; j++) {
            __half2 h = __floats2half2_rn(val[q * 8 + 2 * j], val[q * 8 + 2 * j + 1]);
            op[j] = *(unsigned*)&h;
        }
        out[q] = o;
    }

    int g = batch[n];
    int r = n & (NREP - 1);
    float* base = g_Shr + ((size_t)(r * N_GRAPHS + g)) * HID;
#pragma unroll
    for (int i = 0; i < HID / 4; i++)
        red4(base + 4 * i, val[4 * i], val[4 * i + 1], val[4 * i + 2], val[4 * i + 3]);
    atomicAdd(&g_cntr[r * N_GRAPHS + g], 1.0f);
}

// ---------------- K3: sorted layer-2 aggregation (R7-exact) ------------------
__global__ void k_edge2s() {
    int t    = blockIdx.x * blockDim.x + threadIdx.x;
    int w    = t >> 5;
    int lane = t & 31;
    int e0   = w * CHUNK;
    if (e0 >= N_EDGES) return;
    int r = w & (NREP - 1);

    float ax = 0.f, ay = 0.f;
    int cur = -1;
    const ull* R = g_rec;
#pragma unroll 4
    for (int e = e0; e < e0 + CHUNK; e += 2) {
        ulonglong2 rr = *(const ulonglong2*)(R + e);
        int srcA = (int)(rr.x & 0xFFFFF), gA = (int)((rr.x >> 40) & 0xFF);
        int srcB = (int)(rr.y & 0xFFFFF), gB = (int)((rr.y >> 40) & 0xFF);
        float2 fA = __half22float2(*(const __half2*)(g_h1h + (size_t)srcA * HID + lane * 2));
        float2 fB = __half22float2(*(const __half2*)(g_h1h + (size_t)srcB * HID + lane * 2));
        if (gA != cur) {
            if (cur >= 0) red2(g_S2 + ((size_t)(r * N_GRAPHS + cur)) * HID + lane * 2, ax, ay);
            ax = 0.f; ay = 0.f; cur = gA;
        }
        ax += fA.x; ay += fA.y;
        if (gB != cur) {
            red2(g_S2 + ((size_t)(r * N_GRAPHS + cur)) * HID + lane * 2, ax, ay);
            ax = 0.f; ay = 0.f; cur = gB;
        }
        ax += fB.x; ay += fB.y;
    }
    if (cur >= 0) red2(g_S2 + ((size_t)(r * N_GRAPHS + cur)) * HID + lane * 2, ax, ay);
}

// ---------------- K4: reduce replicas + tiny GEMM + mean + relu (R7-exact) ---
__global__ void k_final(const float* __restrict__ w2_rel,
                        const float* __restrict__ b2,
                        const float* __restrict__ w2_root,
                        float* __restrict__ out) {
    int g = blockIdx.x;
    int c = threadIdx.x;
    __shared__ float sA[HID];
    __shared__ float sH[HID];
    __shared__ float sc;

    float s2 = 0.0f, sh = 0.0f;
#pragma unroll
    for (int r = 0; r < NREP; r++) {
        s2 += g_S2 [((size_t)(r * N_GRAPHS + g)) * HID + c];
        sh += g_Shr[((size_t)(r * N_GRAPHS + g)) * HID + c];
    }
    sA[c] = s2;
    sH[c] = sh;
    if (c == 0) {
        float n = 0.0f;
#pragma unroll
        for (int r = 0; r < NREP; r++) n += g_cntr[r * N_GRAPHS + g];
        sc = n;
    }
    __syncthreads();

    float acc = 0.0f;
#pragma unroll 8
    for (int k = 0; k < HID; k++)
        acc += sA[k] * w2_rel[k * HID + c] + sH[k] * w2_root[k * HID + c];

    float n = sc;
    acc += n * b2[c];
    out[g * HID + c] = fmaxf(acc / fmaxf(n, 1.0f), 0.0f);
}

// ---------------- launch -----------------------------------------------------
extern "C" void kernel_launch(void* const* d_in, const int* in_sizes, int n_in,
                              void* d_out, int out_size) {
    const float* x       = (const float*)d_in[0];
    const int*   ei      = (const int*)d_in[1];
    const int*   batch   = (const int*)d_in[2];
    const float* w1_rel  = (const float*)d_in[3];
    const float* b1_rel  = (const float*)d_in[4];
    const float* w1_root = (const float*)d_in[5];
    const float* w2_rel  = (const float*)d_in[6];
    const float* b2_rel  = (const float*)d_in[7];
    const float* w2_root = (const float*)d_in[8];
    float*       out     = (float*)d_out;

    int nwarp = N_EDGES / CHUNK;                       // 12500, exact
    int ncta  = (nwarp * 32 + 255) / 256;              // 1563

    k_init   <<<2048, 256>>>(x, ei);                   // zeroing + convert + fused hist
    k_scan1  <<<NSB, 1024>>>();
    k_scan2  <<<NSB, 1024>>>();
    k_scatter<<<2048, 256>>>(ei, batch);
    k_edge1s <<<ncta, 256>>>();
    k_node1  <<<(N_NODES + 127) / 128, 128>>>(w1_rel, b1_rel, w1_root, batch);
    k_edge2s <<<ncta, 256>>>();
    k_final  <<<N_GRAPHS, HID>>>(w2_rel, b2_rel, w2_root, out);
}

// round 14
// speedup vs baseline: 1.6615x; 1.1445x over previous
#include <cuda_runtime.h>
#include <cuda_fp16.h>
#include <cstdint>

#define N_NODES  100000
#define N_EDGES  1600000
#define N_GRAPHS 256
#define F_IN     38
#define FP       40      // padded feature width (80B half rows)
#define HID      64
#define NREP     32      // replicated graph buckets
#define NSB      98      // scan blocks (98*1024 = 100352 bins >= N_NODES)
#define NBINS    (NSB * 1024)

typedef unsigned long long ull;

// ---------------- scratch (static device globals; zero at load) --------------
__device__ __align__(256) __half   g_xh   [N_NODES * FP];          // 8 MB
__device__ __align__(256) float    g_agg1 [N_NODES * FP];          // 16 MB (fully overwritten)
__device__ __align__(256) __half   g_h1h  [N_NODES * HID];         // 12.8MB (overwritten)
__device__ __align__(256) float    g_S2   [NREP * N_GRAPHS * HID]; // 2 MB
__device__ __align__(256) float    g_Shr  [NREP * N_GRAPHS * HID]; // 2 MB
__device__ __align__(256) float    g_cntr [NREP * N_GRAPHS];       // 32 KB
__device__ __align__(256) unsigned g_dcnt [NBINS];                 // 400 KB (scan1 self-zeros)
__device__ __align__(256) unsigned g_base [NBINS];                 // 400 KB (cursor -> end offsets)
__device__ __align__(256) unsigned g_start[NBINS];                 // 400 KB (CSR row starts)
__device__ __align__(256) unsigned g_bsum [128];
__device__ __align__(256) unsigned g_srcs [N_EDGES];               // 6.4 MB dst-sorted src ids

// ---------------- helpers ----------------------------------------------------
__device__ __forceinline__ void red4(float* p, float a, float b, float c, float d) {
    asm volatile("red.global.add.v4.f32 [%0], {%1,%2,%3,%4};"
                 :: "l"(p), "f"(a), "f"(b), "f"(c), "f"(d));
}
__device__ __forceinline__ void red2(float* p, float a, float b) {
    asm volatile("red.global.add.v2.f32 [%0], {%1,%2};"
                 :: "l"(p), "f"(a), "f"(b));
}
__device__ __forceinline__ ull pk2(float a) {
    ull r; asm("mov.b64 %0, {%1, %1};" : "=l"(r) : "f"(a)); return r;
}
__device__ __forceinline__ void fma2(ull& d, ull a, ull b) {
    asm("fma.rn.f32x2 %0, %1, %2, %0;" : "+l"(d) : "l"(a), "l"(b));
}
__device__ __forceinline__ float2 upk2(ull v) {
    float2 f; asm("mov.b64 {%0, %1}, %2;" : "=f"(f.x), "=f"(f.y) : "l"(v)); return f;
}

// ---------------- K0: zero buckets + pad-convert x + fused dst histogram -----
// g_dcnt is zero on entry (module load / scan1 self-zero). No agg1 zeroing:
// k_edge1n overwrites every row.
__global__ void k_init(const float* __restrict__ x, const int* __restrict__ ei) {
    int stride = gridDim.x * blockDim.x;
    int tid    = blockIdx.x * blockDim.x + threadIdx.x;
    for (int i = tid; i < N_NODES * FP; i += stride) {
        int n = i / FP;
        int c = i - n * FP;
        g_xh[i] = (c < F_IN) ? __float2half(x[n * F_IN + c]) : __half(0.0f);
    }
    float4 z4 = make_float4(0.f, 0.f, 0.f, 0.f);
    for (int i = tid; i < NREP * N_GRAPHS * HID / 4; i += stride) {
        ((float4*)g_S2)[i]  = z4;
        ((float4*)g_Shr)[i] = z4;
    }
    for (int i = tid; i < NREP * N_GRAPHS; i += stride) g_cntr[i] = 0.0f;
    for (int e = tid; e < N_EDGES; e += stride)
        atomicAdd(&g_dcnt[ei[N_EDGES + e]], 1u);
}

// ---------------- S1: per-block exclusive scan + self-zero g_dcnt ------------
__global__ void k_scan1() {
    __shared__ unsigned s[1024];
    int b = blockIdx.x, t = threadIdx.x;
    int i = b * 1024 + t;
    unsigned v = g_dcnt[i];
    g_dcnt[i] = 0u;                       // restore invariant for next call
    s[t] = v;
    __syncthreads();
    for (int off = 1; off < 1024; off <<= 1) {
        unsigned a = (t >= off) ? s[t - off] : 0u;
        __syncthreads();
        s[t] += a;
        __syncthreads();
    }
    unsigned ex = s[t] - v;               // exclusive within block
    g_base[i]  = ex;
    g_start[i] = ex;
    if (t == 1023) g_bsum[b] = s[t];
}

// ---------------- S2: add block offsets --------------------------------------
__global__ void k_scan2() {
    __shared__ unsigned sb[128];
    __shared__ unsigned soff;
    int b = blockIdx.x, t = threadIdx.x;
    if (t < NSB) sb[t] = g_bsum[t];
    __syncthreads();
    if (t == 0) {
        unsigned s = 0;
        for (int i = 0; i < b; i++) s += sb[i];
        soff = s;
    }
    __syncthreads();
    g_base [b * 1024 + t] += soff;
    g_start[b * 1024 + t] += soff;
}

// ---------------- S3: scatter src ids into dst-sorted CSR (1 thread/edge) ----
// Post-condition: g_base[dst] = end offset (cursor fully advanced).
__global__ void k_scatter(const int* __restrict__ ei) {
    int e = blockIdx.x * blockDim.x + threadIdx.x;
    if (e >= N_EDGES) return;
    unsigned src = (unsigned)ei[e];
    unsigned dst = (unsigned)ei[N_EDGES + e];
    unsigned pos = atomicAdd(&g_base[dst], 1u);
    g_srcs[pos] = src;
}

// ---------------- K1: warp-per-dst layer-1 aggregation (NO atomics) ----------
__global__ void k_edge1n() {
    int w    = (blockIdx.x * blockDim.x + threadIdx.x) >> 5;
    int lane = threadIdx.x & 31;
    if (w >= N_NODES) return;
    unsigned s = g_start[w];
    unsigned e = g_base[w];               // end (post-scatter cursor)
    bool act = lane < FP / 2;
    const __half2* X = (const __half2*)g_xh;

    float ax = 0.f, ay = 0.f;
    unsigned i = s;
    for (; i + 4 <= e; i += 4) {          // 4 gathers in flight
        int s0 = g_srcs[i],     s1 = g_srcs[i + 1];
        int s2 = g_srcs[i + 2], s3 = g_srcs[i + 3];
        if (act) {
            float2 f0 = __half22float2(X[(size_t)s0 * (FP/2) + lane]);
            float2 f1 = __half22float2(X[(size_t)s1 * (FP/2) + lane]);
            float2 f2 = __half22float2(X[(size_t)s2 * (FP/2) + lane]);
            float2 f3 = __half22float2(X[(size_t)s3 * (FP/2) + lane]);
            ax += f0.x + f1.x + f2.x + f3.x;
            ay += f0.y + f1.y + f2.y + f3.y;
        }
    }
    for (; i < e; i++) {
        int s0 = g_srcs[i];
        if (act) {
            float2 f = __half22float2(X[(size_t)s0 * (FP/2) + lane]);
            ax += f.x; ay += f.y;
        }
    }
    if (act) *(float2*)(g_agg1 + (size_t)w * FP + lane * 2) = make_float2(ax, ay);
}

// ---------------- K2: node transform + fused pooling -------------------------
__global__ __launch_bounds__(128) void k_node1(const float* __restrict__ w_rel,
                                               const float* __restrict__ b,
                                               const float* __restrict__ w_root,
                                               const int*   __restrict__ batch) {
    __shared__ __align__(16) float sW[FP * HID * 2 + HID];
    float* sWrel  = sW;
    float* sWroot = sW + FP * HID;
    float* sB     = sW + 2 * FP * HID;
    for (int i = threadIdx.x; i < FP * HID; i += blockDim.x) {
        int k = i / HID;
        int c = i - k * HID;
        sWrel[i]  = (k < F_IN) ? w_rel [k * HID + c] : 0.0f;
        sWroot[i] = (k < F_IN) ? w_root[k * HID + c] : 0.0f;
    }
    for (int i = threadIdx.x; i < HID; i += blockDim.x) sB[i] = b[i];
    __syncthreads();

    int n = blockIdx.x * blockDim.x + threadIdx.x;
    if (n >= N_NODES) return;

    ull acc2[HID / 2];
#pragma unroll
    for (int j = 0; j < HID / 2; j++) acc2[j] = ((const ull*)sB)[j];

    const float4* ar  = (const float4*)(g_agg1 + (size_t)n * FP);
    const uint4*  xrh = (const uint4*) (g_xh   + (size_t)n * FP);

    for (int ch = 0; ch < 5; ch++) {
        float4 a0 = ar[2 * ch];
        float4 a1 = ar[2 * ch + 1];
        uint4  xv = xrh[ch];
        const __half2* hp = (const __half2*)&xv;
        float av[8] = {a0.x, a0.y, a0.z, a0.w, a1.x, a1.y, a1.z, a1.w};
        float xf[8];
#pragma unroll
        for (int j = 0; j < 4; j++) {
            float2 f = __half22float2(hp[j]);
            xf[2 * j] = f.x; xf[2 * j + 1] = f.y;
        }
#pragma unroll
        for (int kk = 0; kk < 8; kk++) {
            int k = ch * 8 + kk;
            ull a2 = pk2(av[kk]);
            ull x2 = pk2(xf[kk]);
            const ulonglong2* wr = (const ulonglong2*)(sWrel  + k * HID);
            const ulonglong2* wo = (const ulonglong2*)(sWroot + k * HID);
#pragma unroll
            for (int c4 = 0; c4 < HID / 4; c4++) {
                ulonglong2 w = wr[c4];
                ulonglong2 u = wo[c4];
                fma2(acc2[2 * c4],     a2, w.x);
                fma2(acc2[2 * c4 + 1], a2, w.y);
                fma2(acc2[2 * c4],     x2, u.x);
                fma2(acc2[2 * c4 + 1], x2, u.y);
            }
        }
    }

    float val[HID];
#pragma unroll
    for (int j = 0; j < HID / 2; j++) {
        float2 f = upk2(acc2[j]);
        val[2 * j]     = fmaxf(f.x, 0.0f);
        val[2 * j + 1] = fmaxf(f.y, 0.0f);
    }

    uint4* out = (uint4*)(g_h1h + (size_t)n * HID);
#pragma unroll
    for (int q = 0; q < 8; q++) {
        uint4 o;
        unsigned* op = (unsigned*)&o;
#pragma unroll
        for (int j = 0; j < 4; j++) {
            __half2 h = __floats2half2_rn(val[q * 8 + 2 * j], val[q * 8 + 2 * j + 1]);
            op[j] = *(unsigned*)&h;
        }
        out[q] = o;
    }

    int g = batch[n];
    int r = n & (NREP - 1);
    float* base = g_Shr + ((size_t)(r * N_GRAPHS + g)) * HID;
#pragma unroll
    for (int i = 0; i < HID / 4; i++)
        red4(base + 4 * i, val[4 * i], val[4 * i + 1], val[4 * i + 2], val[4 * i + 3]);
    atomicAdd(&g_cntr[r * N_GRAPHS + g], 1.0f);
}

// ---------------- K3: warp-per-dst layer-2 aggregation (1 red2 per node) -----
__global__ void k_edge2n(const int* __restrict__ batch) {
    int w    = (blockIdx.x * blockDim.x + threadIdx.x) >> 5;
    int lane = threadIdx.x & 31;
    if (w >= N_NODES) return;
    unsigned s = g_start[w];
    unsigned e = g_base[w];
    if (s == e) return;                   // deg-0: contributes nothing
    const __half2* H = (const __half2*)g_h1h;

    float ax = 0.f, ay = 0.f;
    unsigned i = s;
    for (; i + 4 <= e; i += 4) {
        int s0 = g_srcs[i],     s1 = g_srcs[i + 1];
        int s2 = g_srcs[i + 2], s3 = g_srcs[i + 3];
        float2 f0 = __half22float2(H[(size_t)s0 * (HID/2) + lane]);
        float2 f1 = __half22float2(H[(size_t)s1 * (HID/2) + lane]);
        float2 f2 = __half22float2(H[(size_t)s2 * (HID/2) + lane]);
        float2 f3 = __half22float2(H[(size_t)s3 * (HID/2) + lane]);
        ax += f0.x + f1.x + f2.x + f3.x;
        ay += f0.y + f1.y + f2.y + f3.y;
    }
    for (; i < e; i++) {
        float2 f = __half22float2(H[(size_t)g_srcs[i] * (HID/2) + lane]);
        ax += f.x; ay += f.y;
    }
    int g = batch[w];
    int r = w & (NREP - 1);
    red2(g_S2 + ((size_t)(r * N_GRAPHS + g)) * HID + lane * 2, ax, ay);
}

// ---------------- K4: reduce replicas + tiny GEMM + mean + relu --------------
__global__ void k_final(const float* __restrict__ w2_rel,
                        const float* __restrict__ b2,
                        const float* __restrict__ w2_root,
                        float* __restrict__ out) {
    int g = blockIdx.x;
    int c = threadIdx.x;
    __shared__ float sA[HID];
    __shared__ float sH[HID];
    __shared__ float sc;

    float s2 = 0.0f, sh = 0.0f;
#pragma unroll
    for (int r = 0; r < NREP; r++) {
        s2 += g_S2 [((size_t)(r * N_GRAPHS + g)) * HID + c];
        sh += g_Shr[((size_t)(r * N_GRAPHS + g)) * HID + c];
    }
    sA[c] = s2;
    sH[c] = sh;
    if (c == 0) {
        float n = 0.0f;
#pragma unroll
        for (int r = 0; r < NREP; r++) n += g_cntr[r * N_GRAPHS + g];
        sc = n;
    }
    __syncthreads();

    float acc = 0.0f;
#pragma unroll 8
    for (int k = 0; k < HID; k++)
        acc += sA[k] * w2_rel[k * HID + c] + sH[k] * w2_root[k * HID + c];

    float n = sc;
    acc += n * b2[c];
    out[g * HID + c] = fmaxf(acc / fmaxf(n, 1.0f), 0.0f);
}

// ---------------- launch -----------------------------------------------------
extern "C" void kernel_launch(void* const* d_in, const int* in_sizes, int n_in,
                              void* d_out, int out_size) {
    const float* x       = (const float*)d_in[0];
    const int*   ei      = (const int*)d_in[1];
    const int*   batch   = (const int*)d_in[2];
    const float* w1_rel  = (const float*)d_in[3];
    const float* b1_rel  = (const float*)d_in[4];
    const float* w1_root = (const float*)d_in[5];
    const float* w2_rel  = (const float*)d_in[6];
    const float* b2_rel  = (const float*)d_in[7];
    const float* w2_root = (const float*)d_in[8];
    float*       out     = (float*)d_out;

    int ncta_n = (N_NODES * 32 + 255) / 256;           // warp-per-node kernels

    k_init   <<<2048, 256>>>(x, ei);
    k_scan1  <<<NSB, 1024>>>();
    k_scan2  <<<NSB, 1024>>>();
    k_scatter<<<(N_EDGES + 255) / 256, 256>>>(ei);
    k_edge1n <<<ncta_n, 256>>>();
    k_node1  <<<(N_NODES + 127) / 128, 128>>>(w1_rel, b1_rel, w1_root, batch);
    k_edge2n <<<ncta_n, 256>>>(batch);
    k_final  <<<N_GRAPHS, HID>>>(w2_rel, b2_rel, w2_root, out);
}

// round 17
// speedup vs baseline: 1.7022x; 1.0245x over previous
#include <cuda_runtime.h>
#include <cuda_fp16.h>
#include <cstdint>

#define N_NODES  100000
#define N_EDGES  1600000
#define N_GRAPHS 256
#define F_IN     38
#define FP       40      // padded feature width (80B half rows)
#define HID      64
#define NREP     32      // replicated graph buckets
#define NSB      98      // scan blocks (98*1024 = 100352 bins >= N_NODES)
#define NBINS    (NSB * 1024)

typedef unsigned long long ull;

// ---------------- scratch (static device globals; zero at load) --------------
__device__ __align__(256) __half   g_xh   [N_NODES * FP];          // 8 MB
__device__ __align__(256) float    g_agg1 [N_NODES * FP];          // 16 MB (fully overwritten)
__device__ __align__(256) __half   g_h1h  [N_NODES * HID];         // 12.8MB (overwritten)
__device__ __align__(256) float    g_S2   [NREP * N_GRAPHS * HID]; // 2 MB
__device__ __align__(256) float    g_Shr  [NREP * N_GRAPHS * HID]; // 2 MB
__device__ __align__(256) float    g_cntr [NREP * N_GRAPHS];       // 32 KB
__device__ __align__(256) unsigned g_dcnt [NBINS];                 // 400 KB (scan1 self-zeros)
__device__ __align__(256) unsigned g_base [NBINS];                 // block-LOCAL cursor -> end
__device__ __align__(256) unsigned g_start[NBINS];                 // block-LOCAL row starts
__device__ __align__(256) unsigned g_bsum [128];                   // per-block totals
__device__ __align__(256) unsigned g_boff [128];                   // exclusive block offsets
__device__ __align__(256) unsigned g_srcs [N_EDGES];               // 6.4 MB dst-sorted src ids

// ---------------- helpers ----------------------------------------------------
__device__ __forceinline__ void red4(float* p, float a, float b, float c, float d) {
    asm volatile("red.global.add.v4.f32 [%0], {%1,%2,%3,%4};"
                 :: "l"(p), "f"(a), "f"(b), "f"(c), "f"(d));
}
__device__ __forceinline__ void red2(float* p, float a, float b) {
    asm volatile("red.global.add.v2.f32 [%0], {%1,%2};"
                 :: "l"(p), "f"(a), "f"(b));
}
__device__ __forceinline__ ull pk2(float a) {
    ull r; asm("mov.b64 %0, {%1, %1};" : "=l"(r) : "f"(a)); return r;
}
__device__ __forceinline__ void fma2(ull& d, ull a, ull b) {
    asm("fma.rn.f32x2 %0, %1, %2, %0;" : "+l"(d) : "l"(a), "l"(b));
}
__device__ __forceinline__ float2 upk2(ull v) {
    float2 f; asm("mov.b64 {%0, %1}, %2;" : "=f"(f.x), "=f"(f.y) : "l"(v)); return f;
}

// ---------------- K0: zero buckets + pad-convert x + fused dst histogram -----
__global__ void k_init(const float* __restrict__ x, const int* __restrict__ ei) {
    int stride = gridDim.x * blockDim.x;
    int tid    = blockIdx.x * blockDim.x + threadIdx.x;
    for (int i = tid; i < N_NODES * FP; i += stride) {
        int n = i / FP;
        int c = i - n * FP;
        g_xh[i] = (c < F_IN) ? __float2half(x[n * F_IN + c]) : __half(0.0f);
    }
    float4 z4 = make_float4(0.f, 0.f, 0.f, 0.f);
    for (int i = tid; i < NREP * N_GRAPHS * HID / 4; i += stride) {
        ((float4*)g_S2)[i]  = z4;
        ((float4*)g_Shr)[i] = z4;
    }
    for (int i = tid; i < NREP * N_GRAPHS; i += stride) g_cntr[i] = 0.0f;
    for (int e = tid; e < N_EDGES; e += stride)
        atomicAdd(&g_dcnt[ei[N_EDGES + e]], 1u);
}

// ---------------- S1: block-local exclusive scan (shuffle) + self-zero -------
__global__ void k_scan1() {
    __shared__ unsigned ws[32];
    int b    = blockIdx.x, t = threadIdx.x;
    int lane = t & 31, wid = t >> 5;
    int i    = b * 1024 + t;
    unsigned v = g_dcnt[i];
    g_dcnt[i] = 0u;                       // restore invariant for next call

    unsigned xv = v;                      // warp inclusive scan
#pragma unroll
    for (int d = 1; d < 32; d <<= 1) {
        unsigned y = __shfl_up_sync(0xffffffffu, xv, d);
        if (lane >= d) xv += y;
    }
    if (lane == 31) ws[wid] = xv;
    __syncthreads();
    if (wid == 0) {
        unsigned t2 = ws[lane];
#pragma unroll
        for (int d = 1; d < 32; d <<= 1) {
            unsigned y = __shfl_up_sync(0xffffffffu, t2, d);
            if (lane >= d) t2 += y;
        }
        ws[lane] = t2;
    }
    __syncthreads();
    unsigned inc = xv + (wid ? ws[wid - 1] : 0u);   // block-inclusive
    unsigned ex  = inc - v;                         // block-local exclusive
    g_base[i]  = ex;
    g_start[i] = ex;
    if (t == 1023) g_bsum[b] = inc;
}

// ---------------- S2: tiny scan of 98 block sums -> g_boff -------------------
__global__ void k_scanB() {
    __shared__ unsigned ws[4];
    int t = threadIdx.x;                  // 128 threads
    int lane = t & 31, wid = t >> 5;
    unsigned v = (t < NSB) ? g_bsum[t] : 0u;
    unsigned xv = v;
#pragma unroll
    for (int d = 1; d < 32; d <<= 1) {
        unsigned y = __shfl_up_sync(0xffffffffu, xv, d);
        if (lane >= d) xv += y;
    }
    if (lane == 31) ws[wid] = xv;
    __syncthreads();
    unsigned woff = 0;
#pragma unroll
    for (int k = 0; k < 4; k++) if (k < wid) woff += ws[k];
    if (t < NSB) g_boff[t] = xv + woff - v;         // global exclusive offset
}

// ---------------- S3: scatter, 4 edges/thread via int4 (ILP) -----------------
// Post-condition: g_base[dst] = local end offset (cursor advanced).
__global__ void k_scatter(const int* __restrict__ ei) {
    int t = blockIdx.x * blockDim.x + threadIdx.x;  // N_EDGES/4 threads exact
    if (t >= N_EDGES / 4) return;
    int4 s4 = ((const int4*)ei)[t];
    int4 d4 = ((const int4*)(ei + N_EDGES))[t];
    unsigned b0 = g_boff[(unsigned)d4.x >> 10];
    unsigned b1 = g_boff[(unsigned)d4.y >> 10];
    unsigned b2 = g_boff[(unsigned)d4.z >> 10];
    unsigned b3 = g_boff[(unsigned)d4.w >> 10];
    unsigned p0 = atomicAdd(&g_base[d4.x], 1u);
    unsigned p1 = atomicAdd(&g_base[d4.y], 1u);
    unsigned p2 = atomicAdd(&g_base[d4.z], 1u);
    unsigned p3 = atomicAdd(&g_base[d4.w], 1u);
    g_srcs[p0 + b0] = (unsigned)s4.x;
    g_srcs[p1 + b1] = (unsigned)s4.y;
    g_srcs[p2 + b2] = (unsigned)s4.z;
    g_srcs[p3 + b3] = (unsigned)s4.w;
}

// ---------------- K1: warp-per-dst layer-1 aggregation (NO atomics) ----------
__global__ void k_edge1n() {
    int w    = (blockIdx.x * blockDim.x + threadIdx.x) >> 5;
    int lane = threadIdx.x & 31;
    if (w >= N_NODES) return;
    unsigned boff = g_boff[(unsigned)w >> 10];
    unsigned s = g_start[w] + boff;
    unsigned e = g_base[w] + boff;
    bool act = lane < FP / 2;
    const __half2* X = (const __half2*)g_xh;

    float ax = 0.f, ay = 0.f;
    unsigned i = s;
    for (; i + 8 <= e; i += 8) {          // 8 gathers in flight
        int sid[8];
#pragma unroll
        for (int j = 0; j < 8; j++) sid[j] = g_srcs[i + j];
        if (act) {
#pragma unroll
            for (int j = 0; j < 8; j++) {
                float2 f = __half22float2(X[(size_t)sid[j] * (FP/2) + lane]);
                ax += f.x; ay += f.y;
            }
        }
    }
    for (; i < e; i++) {
        int s0 = g_srcs[i];
        if (act) {
            float2 f = __half22float2(X[(size_t)s0 * (FP/2) + lane]);
            ax += f.x; ay += f.y;
        }
    }
    if (act) *(float2*)(g_agg1 + (size_t)w * FP + lane * 2) = make_float2(ax, ay);
}

// ---------------- K2: node transform + fused pooling -------------------------
__global__ __launch_bounds__(128) void k_node1(const float* __restrict__ w_rel,
                                               const float* __restrict__ b,
                                               const float* __restrict__ w_root,
                                               const int*   __restrict__ batch) {
    __shared__ __align__(16) float sW[FP * HID * 2 + HID];
    float* sWrel  = sW;
    float* sWroot = sW + FP * HID;
    float* sB     = sW + 2 * FP * HID;
    for (int i = threadIdx.x; i < FP * HID; i += blockDim.x) {
        int k = i / HID;
        int c = i - k * HID;
        sWrel[i]  = (k < F_IN) ? w_rel [k * HID + c] : 0.0f;
        sWroot[i] = (k < F_IN) ? w_root[k * HID + c] : 0.0f;
    }
    for (int i = threadIdx.x; i < HID; i += blockDim.x) sB[i] = b[i];
    __syncthreads();

    int n = blockIdx.x * blockDim.x + threadIdx.x;
    if (n >= N_NODES) return;

    ull acc2[HID / 2];
#pragma unroll
    for (int j = 0; j < HID / 2; j++) acc2[j] = ((const ull*)sB)[j];

    const float4* ar  = (const float4*)(g_agg1 + (size_t)n * FP);
    const uint4*  xrh = (const uint4*) (g_xh   + (size_t)n * FP);

    for (int ch = 0; ch < 5; ch++) {
        float4 a0 = ar[2 * ch];
        float4 a1 = ar[2 * ch + 1];
        uint4  xv = xrh[ch];
        const __half2* hp = (const __half2*)&xv;
        float av[8] = {a0.x, a0.y, a0.z, a0.w, a1.x, a1.y, a1.z, a1.w};
        float xf[8];
#pragma unroll
        for (int j = 0; j < 4; j++) {
            float2 f = __half22float2(hp[j]);
            xf[2 * j] = f.x; xf[2 * j + 1] = f.y;
        }
#pragma unroll
        for (int kk = 0; kk < 8; kk++) {
            int k = ch * 8 + kk;
            ull a2 = pk2(av[kk]);
            ull x2 = pk2(xf[kk]);
            const ulonglong2* wr = (const ulonglong2*)(sWrel  + k * HID);
            const ulonglong2* wo = (const ulonglong2*)(sWroot + k * HID);
#pragma unroll
            for (int c4 = 0; c4 < HID / 4; c4++) {
                ulonglong2 w = wr[c4];
                ulonglong2 u = wo[c4];
                fma2(acc2[2 * c4],     a2, w.x);
                fma2(acc2[2 * c4 + 1], a2, w.y);
                fma2(acc2[2 * c4],     x2, u.x);
                fma2(acc2[2 * c4 + 1], x2, u.y);
            }
        }
    }

    float val[HID];
#pragma unroll
    for (int j = 0; j < HID / 2; j++) {
        float2 f = upk2(acc2[j]);
        val[2 * j]     = fmaxf(f.x, 0.0f);
        val[2 * j + 1] = fmaxf(f.y, 0.0f);
    }

    uint4* out = (uint4*)(g_h1h + (size_t)n * HID);
#pragma unroll
    for (int q = 0; q < 8; q++) {
        uint4 o;
        unsigned* op = (unsigned*)&o;
#pragma unroll
        for (int j = 0; j < 4; j++) {
            __half2 h = __floats2half2_rn(val[q * 8 + 2 * j], val[q * 8 + 2 * j + 1]);
            op[j] = *(unsigned*)&h;
        }
        out[q] = o;
    }

    int g = batch[n];
    int r = n & (NREP - 1);
    float* base = g_Shr + ((size_t)(r * N_GRAPHS + g)) * HID;
#pragma unroll
    for (int i = 0; i < HID / 4; i++)
        red4(base + 4 * i, val[4 * i], val[4 * i + 1], val[4 * i + 2], val[4 * i + 3]);
    atomicAdd(&g_cntr[r * N_GRAPHS + g], 1.0f);
}

// ---------------- K3: warp-per-dst layer-2 aggregation (1 red2 per node) -----
__global__ void k_edge2n(const int* __restrict__ batch) {
    int w    = (blockIdx.x * blockDim.x + threadIdx.x) >> 5;
    int lane = threadIdx.x & 31;
    if (w >= N_NODES) return;
    unsigned boff = g_boff[(unsigned)w >> 10];
    unsigned s = g_start[w] + boff;
    unsigned e = g_base[w] + boff;
    if (s == e) return;                   // deg-0: contributes nothing
    const __half2* H = (const __half2*)g_h1h;

    float ax = 0.f, ay = 0.f;
    unsigned i = s;
    for (; i + 8 <= e; i += 8) {          // 8 gathers in flight
        int sid[8];
#pragma unroll
        for (int j = 0; j < 8; j++) sid[j] = g_srcs[i + j];
#pragma unroll
        for (int j = 0; j < 8; j++) {
            float2 f = __half22float2(H[(size_t)sid[j] * (HID/2) + lane]);
            ax += f.x; ay += f.y;
        }
    }
    for (; i < e; i++) {
        float2 f = __half22float2(H[(size_t)g_srcs[i] * (HID/2) + lane]);
        ax += f.x; ay += f.y;
    }
    int g = batch[w];
    int r = w & (NREP - 1);
    red2(g_S2 + ((size_t)(r * N_GRAPHS + g)) * HID + lane * 2, ax, ay);
}

// ---------------- K4: reduce replicas + tiny GEMM + mean + relu --------------
__global__ void k_final(const float* __restrict__ w2_rel,
                        const float* __restrict__ b2,
                        const float* __restrict__ w2_root,
                        float* __restrict__ out) {
    int g = blockIdx.x;
    int c = threadIdx.x;
    __shared__ float sA[HID];
    __shared__ float sH[HID];
    __shared__ float sc;

    float s2 = 0.0f, sh = 0.0f;
#pragma unroll
    for (int r = 0; r < NREP; r++) {
        s2 += g_S2 [((size_t)(r * N_GRAPHS + g)) * HID + c];
        sh += g_Shr[((size_t)(r * N_GRAPHS + g)) * HID + c];
    }
    sA[c] = s2;
    sH[c] = sh;
    if (c == 0) {
        float n = 0.0f;
#pragma unroll
        for (int r = 0; r < NREP; r++) n += g_cntr[r * N_GRAPHS + g];
        sc = n;
    }
    __syncthreads();

    float acc = 0.0f;
#pragma unroll 8
    for (int k = 0; k < HID; k++)
        acc += sA[k] * w2_rel[k * HID + c] + sH[k] * w2_root[k * HID + c];

    float n = sc;
    acc += n * b2[c];
    out[g * HID + c] = fmaxf(acc / fmaxf(n, 1.0f), 0.0f);
}

// ---------------- launch -----------------------------------------------------
extern "C" void kernel_launch(void* const* d_in, const int* in_sizes, int n_in,
                              void* d_out, int out_size) {
    const float* x       = (const float*)d_in[0];
    const int*   ei      = (const int*)d_in[1];
    const int*   batch   = (const int*)d_in[2];
    const float* w1_rel  = (const float*)d_in[3];
    const float* b1_rel  = (const float*)d_in[4];
    const float* w1_root = (const float*)d_in[5];
    const float* w2_rel  = (const float*)d_in[6];
    const float* b2_rel  = (const float*)d_in[7];
    const float* w2_root = (const float*)d_in[8];
    float*       out     = (float*)d_out;

    int ncta_n = (N_NODES * 32 + 255) / 256;           // warp-per-node kernels

    k_init   <<<2048, 256>>>(x, ei);
    k_scan1  <<<NSB, 1024>>>();
    k_scanB  <<<1, 128>>>();
    k_scatter<<<(N_EDGES / 4 + 255) / 256, 256>>>(ei);
    k_edge1n <<<ncta_n, 256>>>();
    k_node1  <<<(N_NODES + 127) / 128, 128>>>(w1_rel, b1_rel, w1_root, batch);
    k_edge2n <<<ncta_n, 256>>>(batch);
    k_final  <<<N_GRAPHS, HID>>>(w2_rel, b2_rel, w2_root, out);
}